// round 13
// baseline (speedup 1.0000x reference)
#include <cuda_runtime.h>
#include <cuda_bf16.h>
#include <cstdint>

#define Bn 8192
#define Dn 512
#define Kn 64
#define Hn 256
#define SN (Kn*Kn + Dn)   // 4608
#define K2C (Hn/2)        // 128 u32 pairs per K=256 row
#define D2C (Dn/2)        // 256 u32 pairs per K=512 row

__device__ float    g_s [Bn * SN];
__device__ float    g_hU[Bn * Kn];
__device__ float    g_h2[Bn * Kn];
__device__ float    g_x1[Bn * Dn];
__device__ float    g_x2[Bn * Dn];
__device__ uint32_t g_h1h[Bn * K2C];
__device__ uint32_t g_h1l[Bn * K2C];
__device__ uint32_t g_w2h[K2C * SN];
__device__ uint32_t g_w2l[K2C * SN];
__device__ uint32_t g_w1h[D2C * Hn];
__device__ uint32_t g_w1l[D2C * Hn];
__device__ uint32_t g_xh [Bn * D2C];
__device__ uint32_t g_xl [Bn * D2C];

// ---------------------------------------------------------------------------
__device__ __forceinline__ void split_pack(float x0, float x1,
                                           uint32_t& hi, uint32_t& lo)
{
    __nv_bfloat16 h0 = __float2bfloat16_rn(x0);
    __nv_bfloat16 h1 = __float2bfloat16_rn(x1);
    __nv_bfloat16 l0 = __float2bfloat16_rn(x0 - __bfloat162float(h0));
    __nv_bfloat16 l1 = __float2bfloat16_rn(x1 - __bfloat162float(h1));
    hi = ((uint32_t)__bfloat16_as_ushort(h1) << 16) | __bfloat16_as_ushort(h0);
    lo = ((uint32_t)__bfloat16_as_ushort(l1) << 16) | __bfloat16_as_ushort(l0);
}

#define MMA_BF16(C0,C1,C2,C3, A0,A1,A2,A3, B0,B1)                          \
    asm volatile(                                                           \
        "mma.sync.aligned.m16n8k16.row.col.f32.bf16.bf16.f32 "              \
        "{%0,%1,%2,%3}, {%4,%5,%6,%7}, {%8,%9}, {%0,%1,%2,%3};\n"           \
        : "+f"(C0), "+f"(C1), "+f"(C2), "+f"(C3)                            \
        : "r"(A0), "r"(A1), "r"(A2), "r"(A3), "r"(B0), "r"(B1))

#define LDSM_X4(R0,R1,R2,R3, addr)                                          \
    asm volatile("ldmatrix.sync.aligned.m8n8.x4.shared.b16 {%0,%1,%2,%3}, [%4];" \
        : "=r"(R0), "=r"(R1), "=r"(R2), "=r"(R3) : "r"(addr))

#define CP16(dst, src) asm volatile("cp.async.cg.shared.global [%0], [%1], 16;" :: "r"(dst), "l"(src))
#define CP8(dst, src)  asm volatile("cp.async.ca.shared.global [%0], [%1], 8;"  :: "r"(dst), "l"(src))
#define CP_COMMIT()    asm volatile("cp.async.commit_group;" ::: "memory")

__device__ __forceinline__ uint32_t smem_u32(const void* p) {
    uint32_t a;
    asm("{ .reg .u64 t; cvta.to.shared.u64 t, %1; cvt.u32.u64 %0, t; }"
        : "=r"(a) : "l"(p));
    return a;
}

// ---------------------------------------------------------------------------
// pre-split helpers.  wsplit permutes columns within each 32-block:
// original col o = nt*8+gid  ->  stored col d = gid*4+nt, so a thread's four
// nt-fragments become one LDS.128 in the tensor kernel.
// ---------------------------------------------------------------------------
__global__ void __launch_bounds__(256)
wsplit_k(const float* __restrict__ W, uint32_t* __restrict__ WH,
         uint32_t* __restrict__ WL, int K2, int N)
{
    int idx = blockIdx.x * 256 + threadIdx.x;
    if (idx >= K2 * N) return;
    int p = idx / N, n = idx % N;
    float a = W[(size_t)(2*p)   * N + n];
    float b = W[(size_t)(2*p+1) * N + n];
    int nt = (n >> 3) & 3, gid = n & 7;
    int d  = (n & ~31) | (gid * 4 + nt);
    split_pack(a, b, WH[(size_t)p * N + d], WL[(size_t)p * N + d]);
}

__global__ void __launch_bounds__(256)
xsplit_k(const float* __restrict__ X, uint32_t* __restrict__ XH,
         uint32_t* __restrict__ XL)
{
    int idx = blockIdx.x * 256 + threadIdx.x;   // over Bn*D2C
    float2 v = *(const float2*)(X + (size_t)idx * 2);
    split_pack(v.x, v.y, XH[idx], XL[idx]);
}

// ---------------------------------------------------------------------------
// fp32 SIMT GEMM (hU)
// ---------------------------------------------------------------------------
template<int BM, int BN, int BK, int TM, int TN>
__global__ void __launch_bounds__((BM/TM)*(BN/TN))
gemm_k(const float* __restrict__ A, const float* __restrict__ B,
       float* __restrict__ C, int M, int N, int Kd)
{
    constexpr int NT = (BM/TM)*(BN/TN);
    __shared__ float As[BK][BM + 8];
    __shared__ float Bs[BK][BN];

    const int tid = threadIdx.x;
    const int tx  = tid % (BN/TN);
    const int ty  = tid / (BN/TN);
    const int bm  = blockIdx.y * BM;
    const int bn  = blockIdx.x * BN;

    float acc[TM][TN];
#pragma unroll
    for (int i = 0; i < TM; i++)
#pragma unroll
        for (int j = 0; j < TN; j++) acc[i][j] = 0.f;

    const float* Ag = A + (size_t)bm * Kd;
    const float* Bg = B + bn;

    for (int k0 = 0; k0 < Kd; k0 += BK) {
#pragma unroll
        for (int idx = tid; idx < BM*BK/4; idx += NT) {
            int r  = idx / (BK/4);
            int c4 = (idx % (BK/4)) * 4;
            float4 v = *(const float4*)(Ag + (size_t)r * Kd + k0 + c4);
            As[c4+0][r] = v.x; As[c4+1][r] = v.y;
            As[c4+2][r] = v.z; As[c4+3][r] = v.w;
        }
#pragma unroll
        for (int idx = tid; idx < BK*BN/4; idx += NT) {
            int r  = idx / (BN/4);
            int c4 = (idx % (BN/4)) * 4;
            *(float4*)&Bs[r][c4] = *(const float4*)(Bg + (size_t)(k0 + r) * N + c4);
        }
        __syncthreads();

#pragma unroll
        for (int kk = 0; kk < BK; kk++) {
            float a[TM], b[TN];
#pragma unroll
            for (int i = 0; i < TM; i += 4) {
                float4 v = *(const float4*)&As[kk][ty*TM + i];
                a[i] = v.x; a[i+1] = v.y; a[i+2] = v.z; a[i+3] = v.w;
            }
#pragma unroll
            for (int j = 0; j < TN; j += 4) {
                float4 v = *(const float4*)&Bs[kk][tx*TN + j];
                b[j] = v.x; b[j+1] = v.y; b[j+2] = v.z; b[j+3] = v.w;
            }
#pragma unroll
            for (int i = 0; i < TM; i++)
#pragma unroll
                for (int j = 0; j < TN; j++)
                    acc[i][j] = fmaf(a[i], b[j], acc[i][j]);
        }
        __syncthreads();
    }

#pragma unroll
    for (int i = 0; i < TM; i++) {
        const int row = bm + ty*TM + i;
#pragma unroll
        for (int j = 0; j < TN; j += 4) {
            const int col = bn + tx*TN + j;
            float4 v;
            v.x = acc[i][j+0]; v.y = acc[i][j+1];
            v.z = acc[i][j+2]; v.w = acc[i][j+3];
            *(float4*)(C + (size_t)row * N + col) = v;
        }
    }
}

// ---------------------------------------------------------------------------
// V-gemm: xout = relu(h2 @ V + s[:, :512]); writes fp32 AND split bf16 xh/xl
// ---------------------------------------------------------------------------
__global__ void __launch_bounds__(256)
vgemm_k(const float* __restrict__ A, const float* __restrict__ B,
        const float* __restrict__ bias, int bias_ld,
        float* __restrict__ C, uint32_t* __restrict__ Ch, uint32_t* __restrict__ Cl,
        int M, int N, int Kd)
{
    constexpr int BM=128, BN=128, BK=16, TM=8, TN=8, NT=256;
    __shared__ float As[BK][BM + 8];
    __shared__ float Bs[BK][BN];

    const int tid = threadIdx.x;
    const int tx  = tid % (BN/TN);
    const int ty  = tid / (BN/TN);
    const int bm  = blockIdx.y * BM;
    const int bn  = blockIdx.x * BN;

    float acc[TM][TN];
#pragma unroll
    for (int i = 0; i < TM; i++)
#pragma unroll
        for (int j = 0; j < TN; j++) acc[i][j] = 0.f;

    const float* Ag = A + (size_t)bm * Kd;
    const float* Bg = B + bn;

    for (int k0 = 0; k0 < Kd; k0 += BK) {
#pragma unroll
        for (int idx = tid; idx < BM*BK/4; idx += NT) {
            int r  = idx / (BK/4);
            int c4 = (idx % (BK/4)) * 4;
            float4 v = *(const float4*)(Ag + (size_t)r * Kd + k0 + c4);
            As[c4+0][r] = v.x; As[c4+1][r] = v.y;
            As[c4+2][r] = v.z; As[c4+3][r] = v.w;
        }
#pragma unroll
        for (int idx = tid; idx < BK*BN/4; idx += NT) {
            int r  = idx / (BN/4);
            int c4 = (idx % (BN/4)) * 4;
            *(float4*)&Bs[r][c4] = *(const float4*)(Bg + (size_t)(k0 + r) * N + c4);
        }
        __syncthreads();

#pragma unroll
        for (int kk = 0; kk < BK; kk++) {
            float a[TM], b[TN];
#pragma unroll
            for (int i = 0; i < TM; i += 4) {
                float4 v = *(const float4*)&As[kk][ty*TM + i];
                a[i] = v.x; a[i+1] = v.y; a[i+2] = v.z; a[i+3] = v.w;
            }
#pragma unroll
            for (int j = 0; j < TN; j += 4) {
                float4 v = *(const float4*)&Bs[kk][tx*TN + j];
                b[j] = v.x; b[j+1] = v.y; b[j+2] = v.z; b[j+3] = v.w;
            }
#pragma unroll
            for (int i = 0; i < TM; i++)
#pragma unroll
                for (int j = 0; j < TN; j++)
                    acc[i][j] = fmaf(a[i], b[j], acc[i][j]);
        }
        __syncthreads();
    }

    const int N2 = N >> 1;
#pragma unroll
    for (int i = 0; i < TM; i++) {
        const int row = bm + ty*TM + i;
#pragma unroll
        for (int j = 0; j < TN; j += 4) {
            const int col = bn + tx*TN + j;
            float4 bv = *(const float4*)(bias + (size_t)row * bias_ld + col);
            float4 v;
            v.x = fmaxf(acc[i][j+0] + bv.x, 0.f);
            v.y = fmaxf(acc[i][j+1] + bv.y, 0.f);
            v.z = fmaxf(acc[i][j+2] + bv.z, 0.f);
            v.w = fmaxf(acc[i][j+3] + bv.w, 0.f);
            *(float4*)(C + (size_t)row * N + col) = v;
            uint32_t h, l;
            split_pack(v.x, v.y, h, l);
            Ch[(size_t)row * N2 + (col>>1)]     = h;
            Cl[(size_t)row * N2 + (col>>1)]     = l;
            split_pack(v.z, v.w, h, l);
            Ch[(size_t)row * N2 + (col>>1) + 1] = h;
            Cl[(size_t)row * N2 + (col>>1) + 1] = l;
        }
    }
}

// ---------------------------------------------------------------------------
// unified tensor GEMM (pre-split operands), 3-stage cp.async, 1 barrier/chunk.
// B stored column-permuted (see wsplit) -> B fragments are LDS.128.
// OUT=0: C fp32 = A@B + bias[N].  OUT=1: relu(A@B+bias) -> split Ch/Cl.
// ---------------------------------------------------------------------------
#define AS_OFF_L (128*20*4)            // 10240
#define BS_OFF_H (2*128*20*4)          // 20480
#define BS_OFF_L (BS_OFF_H + 16*136*4) // 29184
#define STG_SZ   (BS_OFF_L + 16*136*4) // 37888
#define TC_SMEM  (3*STG_SZ)            // 113664

template<int OUT>
__global__ void __launch_bounds__(256, 2)
tcgemm_k(const uint32_t* __restrict__ AH, const uint32_t* __restrict__ AL,
         const uint32_t* __restrict__ BH, const uint32_t* __restrict__ BL,
         const float* __restrict__ bias, float* __restrict__ Cf,
         uint32_t* __restrict__ Ch, uint32_t* __restrict__ Cl,
         int M, int N, int K2)
{
    extern __shared__ char dsm[];
    const uint32_t sb0 = smem_u32(dsm);

    const int tid  = threadIdx.x;
    const int bm   = blockIdx.y * 128;
    const int bn   = blockIdx.x * 128;
    const int warp = tid >> 5;
    const int lane = tid & 31;
    const int wm   = (warp >> 2) * 64;
    const int wn   = (warp & 3) * 32;
    const int gid  = lane >> 2;
    const int tig  = lane & 3;
    const int NC   = K2 / 16;

    const uint32_t lm_off =
        (uint32_t)(((wm + (lane & 15)) * 20 + ((lane >> 4) << 2)) * 4);

    float c[4][4][4];
#pragma unroll
    for (int mt = 0; mt < 4; mt++)
#pragma unroll
        for (int nt = 0; nt < 4; nt++)
#pragma unroll
            for (int i = 0; i < 4; i++) c[mt][nt][i] = 0.f;

    auto issue = [&](int kc) {
        const uint32_t sb = sb0 + (kc % 3) * STG_SZ;
#pragma unroll
        for (int i = 0; i < 4; i++) {
            int f = tid + i * 256;
            int r = f >> 3, q = f & 7;
            uint32_t d = (uint32_t)(r * 20 + q * 2) * 4;
            size_t   s = (size_t)(bm + r) * K2 + kc * 16 + q * 2;
            CP8(sb + d,            (const char*)(AH + s));
            CP8(sb + AS_OFF_L + d, (const char*)(AL + s));
        }
#pragma unroll
        for (int i = 0; i < 2; i++) {
            int f = tid + i * 256;
            int r = f >> 5, q = f & 31;
            uint32_t d = (uint32_t)(r * 136 + q * 4) * 4;
            size_t   s = (size_t)(kc * 16 + r) * N + bn + q * 4;
            CP16(sb + BS_OFF_H + d, (const char*)(BH + s));
            CP16(sb + BS_OFF_L + d, (const char*)(BL + s));
        }
        CP_COMMIT();
    };

    issue(0);
    issue(1);

    for (int kc = 0; kc < NC; kc++) {
        if (kc + 1 < NC) asm volatile("cp.async.wait_group 1;" ::: "memory");
        else             asm volatile("cp.async.wait_group 0;" ::: "memory");
        __syncthreads();
        if (kc + 2 < NC) issue(kc + 2);

        const int st = kc % 3;
        const uint32_t sbase = sb0 + st * STG_SZ;
        const uint32_t* BsH = (const uint32_t*)(dsm + st * STG_SZ + BS_OFF_H);
        const uint32_t* BsL = (const uint32_t*)(dsm + st * STG_SZ + BS_OFF_L);

#pragma unroll
        for (int ks = 0; ks < 2; ks++) {
            const int pb = ks * 8;
            uint32_t afH[4][4], afL[4][4];
            uint32_t b0H[4], b1H[4], b0L[4], b1L[4];
#pragma unroll
            for (int mt = 0; mt < 4; mt++) {
                uint32_t aH = sbase + lm_off + (uint32_t)((mt * 16 * 20 + pb) * 4);
                LDSM_X4(afH[mt][0], afH[mt][1], afH[mt][2], afH[mt][3], aH);
                LDSM_X4(afL[mt][0], afL[mt][1], afL[mt][2], afL[mt][3], aH + AS_OFF_L);
            }
            // permuted B: one LDS.128 covers nt=0..3 for a given k-row
            {
                const int c0 = wn + (gid << 2);
                *(uint4*)b0H = *(const uint4*)(BsH + (pb + tig    )*136 + c0);
                *(uint4*)b1H = *(const uint4*)(BsH + (pb + tig + 4)*136 + c0);
                *(uint4*)b0L = *(const uint4*)(BsL + (pb + tig    )*136 + c0);
                *(uint4*)b1L = *(const uint4*)(BsL + (pb + tig + 4)*136 + c0);
            }
#pragma unroll
            for (int mt = 0; mt < 4; mt++)
#pragma unroll
                for (int nt = 0; nt < 4; nt++) {
                    MMA_BF16(c[mt][nt][0], c[mt][nt][1], c[mt][nt][2], c[mt][nt][3],
                             afL[mt][0], afL[mt][1], afL[mt][2], afL[mt][3],
                             b0H[nt], b1H[nt]);
                    MMA_BF16(c[mt][nt][0], c[mt][nt][1], c[mt][nt][2], c[mt][nt][3],
                             afH[mt][0], afH[mt][1], afH[mt][2], afH[mt][3],
                             b0L[nt], b1L[nt]);
                    MMA_BF16(c[mt][nt][0], c[mt][nt][1], c[mt][nt][2], c[mt][nt][3],
                             afH[mt][0], afH[mt][1], afH[mt][2], afH[mt][3],
                             b0H[nt], b1H[nt]);
                }
        }
    }

    const int N2 = N >> 1;
#pragma unroll
    for (int mt = 0; mt < 4; mt++) {
        const int row = bm + wm + mt * 16 + gid;
#pragma unroll
        for (int nt = 0; nt < 4; nt++) {
            const int col = bn + wn + nt * 8 + tig * 2;
            float b0 = bias[col], b1 = bias[col + 1];
            if (OUT == 0) {
                float2 v0, v1;
                v0.x = c[mt][nt][0] + b0; v0.y = c[mt][nt][1] + b1;
                v1.x = c[mt][nt][2] + b0; v1.y = c[mt][nt][3] + b1;
                *(float2*)(Cf + (size_t)row * N + col)       = v0;
                *(float2*)(Cf + (size_t)(row + 8) * N + col) = v1;
            } else {
                float v00 = fmaxf(c[mt][nt][0] + b0, 0.f);
                float v01 = fmaxf(c[mt][nt][1] + b1, 0.f);
                float v10 = fmaxf(c[mt][nt][2] + b0, 0.f);
                float v11 = fmaxf(c[mt][nt][3] + b1, 0.f);
                uint32_t h, l;
                split_pack(v00, v01, h, l);
                Ch[(size_t)row * N2 + (col>>1)] = h;
                Cl[(size_t)row * N2 + (col>>1)] = l;
                split_pack(v10, v11, h, l);
                Ch[(size_t)(row+8) * N2 + (col>>1)] = h;
                Cl[(size_t)(row+8) * N2 + (col>>1)] = l;
            }
        }
    }
}

// ---------------------------------------------------------------------------
__global__ void __launch_bounds__(256)
einsum_k(const float* __restrict__ hU, const float* __restrict__ s,
         float* __restrict__ h2)
{
    __shared__ float hs[4][Kn];
    const int tid = threadIdx.x;
    const int r   = tid / Kn;
    const int j   = tid % Kn;
    const int b   = blockIdx.x * 4 + r;

    hs[r][j] = hU[(size_t)b * Kn + j];
    __syncthreads();

    const float* S = s + (size_t)b * SN + Dn;
    float acc = 0.f;
#pragma unroll
    for (int k = 0; k < Kn; k++)
        acc = fmaf(hs[r][k], S[(size_t)k * Kn + j], acc);
    h2[(size_t)b * Kn + j] = acc;
}

__global__ void __launch_bounds__(256)
outproj_k(const float* __restrict__ x, const float* __restrict__ W,
          const float* __restrict__ b, float* __restrict__ out)
{
    const int warp = (blockIdx.x * blockDim.x + threadIdx.x) >> 5;
    const int lane = threadIdx.x & 31;
    const float4* xr = (const float4*)(x + (size_t)warp * Dn);
    const float4* W4 = (const float4*)W;
    float acc = 0.f;
#pragma unroll
    for (int i = lane; i < Dn/4; i += 32) {
        float4 a = xr[i], w = W4[i];
        acc += a.x*w.x + a.y*w.y + a.z*w.z + a.w*w.w;
    }
#pragma unroll
    for (int o = 16; o; o >>= 1) acc += __shfl_xor_sync(0xFFFFFFFFu, acc, o);
    if (lane == 0) out[warp] = acc + b[0];
}

// ---------------------------------------------------------------------------
static void run_layer(const float* xin, bool first_layer,
                      const float* U, const float* V,
                      const float* hW1, const float* hb1,
                      const float* hW2, const float* hb2,
                      float* s, float* hU, float* h2,
                      uint32_t* h1h, uint32_t* h1l,
                      uint32_t* w2h, uint32_t* w2l,
                      uint32_t* w1h, uint32_t* w1l,
                      uint32_t* xh, uint32_t* xl,
                      float* xout)
{
    wsplit_k<<<(K2C*SN + 255)/256, 256>>>(hW2, w2h, w2l, K2C, SN);
    wsplit_k<<<(D2C*Hn + 255)/256, 256>>>(hW1, w1h, w1l, D2C, Hn);
    if (first_layer)
        xsplit_k<<<(Bn*D2C)/256, 256>>>(xin, xh, xl);

    tcgemm_k<1><<<dim3(Hn/128, Bn/128), 256, TC_SMEM>>>(
        xh, xl, w1h, w1l, hb1, nullptr, h1h, h1l, Bn, Hn, D2C);

    gemm_k<32,64,16,4,4><<<dim3(Kn/64, Bn/32), 128>>>(
        xin, U, hU, Bn, Kn, Dn);

    tcgemm_k<0><<<dim3(SN/128, Bn/128), 256, TC_SMEM>>>(
        h1h, h1l, w2h, w2l, hb2, s, nullptr, nullptr, Bn, SN, K2C);

    einsum_k<<<Bn/4, 256>>>(hU, s, h2);

    vgemm_k<<<dim3(Dn/128, Bn/128), 256>>>(
        h2, V, s, SN, xout, xh, xl, Bn, Dn, Kn);
}

extern "C" void kernel_launch(void* const* d_in, const int* in_sizes, int n_in,
                              void* d_out, int out_size)
{
    cudaFuncSetAttribute(tcgemm_k<0>,
                         cudaFuncAttributeMaxDynamicSharedMemorySize, TC_SMEM);
    cudaFuncSetAttribute(tcgemm_k<1>,
                         cudaFuncAttributeMaxDynamicSharedMemorySize, TC_SMEM);

    const float* x    = (const float*)d_in[0];
    const float* Wout = (const float*)d_in[19];
    const float* bout = (const float*)d_in[20];

    float *s, *hU, *h2, *x1, *x2;
    uint32_t *h1h, *h1l, *w2h, *w2l, *w1h, *w1l, *xh, *xl;
    cudaGetSymbolAddress((void**)&s,   g_s);
    cudaGetSymbolAddress((void**)&hU,  g_hU);
    cudaGetSymbolAddress((void**)&h2,  g_h2);
    cudaGetSymbolAddress((void**)&x1,  g_x1);
    cudaGetSymbolAddress((void**)&x2,  g_x2);
    cudaGetSymbolAddress((void**)&h1h, g_h1h);
    cudaGetSymbolAddress((void**)&h1l, g_h1l);
    cudaGetSymbolAddress((void**)&w2h, g_w2h);
    cudaGetSymbolAddress((void**)&w2l, g_w2l);
    cudaGetSymbolAddress((void**)&w1h, g_w1h);
    cudaGetSymbolAddress((void**)&w1l, g_w1l);
    cudaGetSymbolAddress((void**)&xh,  g_xh);
    cudaGetSymbolAddress((void**)&xl,  g_xl);

    const float* U1  = (const float*)d_in[1];
    const float* V1  = (const float*)d_in[2];
    const float* W11 = (const float*)d_in[3];
    const float* b11 = (const float*)d_in[4];
    const float* W21 = (const float*)d_in[5];
    const float* b21 = (const float*)d_in[6];

    const float* U2  = (const float*)d_in[7];
    const float* V2  = (const float*)d_in[8];
    const float* W12 = (const float*)d_in[9];
    const float* b12 = (const float*)d_in[10];
    const float* W22 = (const float*)d_in[11];
    const float* b22 = (const float*)d_in[12];

    const float* U3  = (const float*)d_in[13];
    const float* V3  = (const float*)d_in[14];
    const float* W13 = (const float*)d_in[15];
    const float* b13 = (const float*)d_in[16];
    const float* W23 = (const float*)d_in[17];
    const float* b23 = (const float*)d_in[18];

    run_layer(x,  true,  U1, V1, W11, b11, W21, b21,
              s, hU, h2, h1h, h1l, w2h, w2l, w1h, w1l, xh, xl, x1);
    run_layer(x1, false, U2, V2, W12, b12, W22, b22,
              s, hU, h2, h1h, h1l, w2h, w2l, w1h, w1l, xh, xl, x2);
    run_layer(x2, false, U3, V3, W13, b13, W23, b23,
              s, hU, h2, h1h, h1l, w2h, w2l, w1h, w1l, xh, xl, x1);

    outproj_k<<<Bn/8, 256>>>(x1, Wout, bout, (float*)d_out);
}

// round 14
// speedup vs baseline: 1.1082x; 1.1082x over previous
#include <cuda_runtime.h>
#include <cuda_bf16.h>
#include <cstdint>

#define Bn 8192
#define Dn 512
#define Kn 64
#define Hn 256
#define SN (Kn*Kn + Dn)   // 4608
#define K2C (Hn/2)        // 128 u32 pairs per K=256 row
#define D2C (Dn/2)        // 256 u32 pairs per K=512 row

__device__ float    g_s [Bn * SN];
__device__ float    g_hU[Bn * Kn];
__device__ float    g_h2[Bn * Kn];
__device__ float    g_x1[Bn * Dn];
__device__ float    g_x2[Bn * Dn];
__device__ uint32_t g_h1h[Bn * K2C];
__device__ uint32_t g_h1l[Bn * K2C];
__device__ uint32_t g_w2h[K2C * SN];
__device__ uint32_t g_w2l[K2C * SN];
__device__ uint32_t g_w1h[D2C * Hn];
__device__ uint32_t g_w1l[D2C * Hn];
__device__ uint32_t g_xh [Bn * D2C];
__device__ uint32_t g_xl [Bn * D2C];

// ---------------------------------------------------------------------------
__device__ __forceinline__ void split_pack(float x0, float x1,
                                           uint32_t& hi, uint32_t& lo)
{
    __nv_bfloat16 h0 = __float2bfloat16_rn(x0);
    __nv_bfloat16 h1 = __float2bfloat16_rn(x1);
    __nv_bfloat16 l0 = __float2bfloat16_rn(x0 - __bfloat162float(h0));
    __nv_bfloat16 l1 = __float2bfloat16_rn(x1 - __bfloat162float(h1));
    hi = ((uint32_t)__bfloat16_as_ushort(h1) << 16) | __bfloat16_as_ushort(h0);
    lo = ((uint32_t)__bfloat16_as_ushort(l1) << 16) | __bfloat16_as_ushort(l0);
}

#define MMA_BF16(C0,C1,C2,C3, A0,A1,A2,A3, B0,B1)                          \
    asm volatile(                                                           \
        "mma.sync.aligned.m16n8k16.row.col.f32.bf16.bf16.f32 "              \
        "{%0,%1,%2,%3}, {%4,%5,%6,%7}, {%8,%9}, {%0,%1,%2,%3};\n"           \
        : "+f"(C0), "+f"(C1), "+f"(C2), "+f"(C3)                            \
        : "r"(A0), "r"(A1), "r"(A2), "r"(A3), "r"(B0), "r"(B1))

#define LDSM_X4(R0,R1,R2,R3, addr)                                          \
    asm volatile("ldmatrix.sync.aligned.m8n8.x4.shared.b16 {%0,%1,%2,%3}, [%4];" \
        : "=r"(R0), "=r"(R1), "=r"(R2), "=r"(R3) : "r"(addr))

#define CP16(dst, src) asm volatile("cp.async.cg.shared.global [%0], [%1], 16;" :: "r"(dst), "l"(src))
#define CP8(dst, src)  asm volatile("cp.async.ca.shared.global [%0], [%1], 8;"  :: "r"(dst), "l"(src))
#define CP_COMMIT()    asm volatile("cp.async.commit_group;" ::: "memory")

__device__ __forceinline__ uint32_t smem_u32(const void* p) {
    uint32_t a;
    asm("{ .reg .u64 t; cvta.to.shared.u64 t, %1; cvt.u32.u64 %0, t; }"
        : "=r"(a) : "l"(p));
    return a;
}

// ---------------------------------------------------------------------------
// pre-split helpers (no permutation — R12 layout)
// ---------------------------------------------------------------------------
__global__ void __launch_bounds__(256)
wsplit_k(const float* __restrict__ W, uint32_t* __restrict__ WH,
         uint32_t* __restrict__ WL, int K2, int N)
{
    int idx = blockIdx.x * 256 + threadIdx.x;
    if (idx >= K2 * N) return;
    int p = idx / N, n = idx % N;
    float a = W[(size_t)(2*p)   * N + n];
    float b = W[(size_t)(2*p+1) * N + n];
    split_pack(a, b, WH[idx], WL[idx]);
}

__global__ void __launch_bounds__(256)
xsplit_k(const float* __restrict__ X, uint32_t* __restrict__ XH,
         uint32_t* __restrict__ XL)
{
    int idx = blockIdx.x * 256 + threadIdx.x;   // over Bn*D2C
    float2 v = *(const float2*)(X + (size_t)idx * 2);
    split_pack(v.x, v.y, XH[idx], XL[idx]);
}

// ---------------------------------------------------------------------------
// fp32 SIMT GEMM (hU)
// ---------------------------------------------------------------------------
template<int BM, int BN, int BK, int TM, int TN>
__global__ void __launch_bounds__((BM/TM)*(BN/TN))
gemm_k(const float* __restrict__ A, const float* __restrict__ B,
       float* __restrict__ C, int M, int N, int Kd)
{
    constexpr int NT = (BM/TM)*(BN/TN);
    __shared__ float As[BK][BM + 8];
    __shared__ float Bs[BK][BN];

    const int tid = threadIdx.x;
    const int tx  = tid % (BN/TN);
    const int ty  = tid / (BN/TN);
    const int bm  = blockIdx.y * BM;
    const int bn  = blockIdx.x * BN;

    float acc[TM][TN];
#pragma unroll
    for (int i = 0; i < TM; i++)
#pragma unroll
        for (int j = 0; j < TN; j++) acc[i][j] = 0.f;

    const float* Ag = A + (size_t)bm * Kd;
    const float* Bg = B + bn;

    for (int k0 = 0; k0 < Kd; k0 += BK) {
#pragma unroll
        for (int idx = tid; idx < BM*BK/4; idx += NT) {
            int r  = idx / (BK/4);
            int c4 = (idx % (BK/4)) * 4;
            float4 v = *(const float4*)(Ag + (size_t)r * Kd + k0 + c4);
            As[c4+0][r] = v.x; As[c4+1][r] = v.y;
            As[c4+2][r] = v.z; As[c4+3][r] = v.w;
        }
#pragma unroll
        for (int idx = tid; idx < BK*BN/4; idx += NT) {
            int r  = idx / (BN/4);
            int c4 = (idx % (BN/4)) * 4;
            *(float4*)&Bs[r][c4] = *(const float4*)(Bg + (size_t)(k0 + r) * N + c4);
        }
        __syncthreads();

#pragma unroll
        for (int kk = 0; kk < BK; kk++) {
            float a[TM], b[TN];
#pragma unroll
            for (int i = 0; i < TM; i += 4) {
                float4 v = *(const float4*)&As[kk][ty*TM + i];
                a[i] = v.x; a[i+1] = v.y; a[i+2] = v.z; a[i+3] = v.w;
            }
#pragma unroll
            for (int j = 0; j < TN; j += 4) {
                float4 v = *(const float4*)&Bs[kk][tx*TN + j];
                b[j] = v.x; b[j+1] = v.y; b[j+2] = v.z; b[j+3] = v.w;
            }
#pragma unroll
            for (int i = 0; i < TM; i++)
#pragma unroll
                for (int j = 0; j < TN; j++)
                    acc[i][j] = fmaf(a[i], b[j], acc[i][j]);
        }
        __syncthreads();
    }

#pragma unroll
    for (int i = 0; i < TM; i++) {
        const int row = bm + ty*TM + i;
#pragma unroll
        for (int j = 0; j < TN; j += 4) {
            const int col = bn + tx*TN + j;
            float4 v;
            v.x = acc[i][j+0]; v.y = acc[i][j+1];
            v.z = acc[i][j+2]; v.w = acc[i][j+3];
            *(float4*)(C + (size_t)row * N + col) = v;
        }
    }
}

// ---------------------------------------------------------------------------
// V-gemm: xout = relu(h2 @ V + s[:, :512]); writes fp32 AND split bf16 xh/xl
// ---------------------------------------------------------------------------
__global__ void __launch_bounds__(256)
vgemm_k(const float* __restrict__ A, const float* __restrict__ B,
        const float* __restrict__ bias, int bias_ld,
        float* __restrict__ C, uint32_t* __restrict__ Ch, uint32_t* __restrict__ Cl,
        int M, int N, int Kd)
{
    constexpr int BM=128, BN=128, BK=16, TM=8, TN=8, NT=256;
    __shared__ float As[BK][BM + 8];
    __shared__ float Bs[BK][BN];

    const int tid = threadIdx.x;
    const int tx  = tid % (BN/TN);
    const int ty  = tid / (BN/TN);
    const int bm  = blockIdx.y * BM;
    const int bn  = blockIdx.x * BN;

    float acc[TM][TN];
#pragma unroll
    for (int i = 0; i < TM; i++)
#pragma unroll
        for (int j = 0; j < TN; j++) acc[i][j] = 0.f;

    const float* Ag = A + (size_t)bm * Kd;
    const float* Bg = B + bn;

    for (int k0 = 0; k0 < Kd; k0 += BK) {
#pragma unroll
        for (int idx = tid; idx < BM*BK/4; idx += NT) {
            int r  = idx / (BK/4);
            int c4 = (idx % (BK/4)) * 4;
            float4 v = *(const float4*)(Ag + (size_t)r * Kd + k0 + c4);
            As[c4+0][r] = v.x; As[c4+1][r] = v.y;
            As[c4+2][r] = v.z; As[c4+3][r] = v.w;
        }
#pragma unroll
        for (int idx = tid; idx < BK*BN/4; idx += NT) {
            int r  = idx / (BN/4);
            int c4 = (idx % (BN/4)) * 4;
            *(float4*)&Bs[r][c4] = *(const float4*)(Bg + (size_t)(k0 + r) * N + c4);
        }
        __syncthreads();

#pragma unroll
        for (int kk = 0; kk < BK; kk++) {
            float a[TM], b[TN];
#pragma unroll
            for (int i = 0; i < TM; i += 4) {
                float4 v = *(const float4*)&As[kk][ty*TM + i];
                a[i] = v.x; a[i+1] = v.y; a[i+2] = v.z; a[i+3] = v.w;
            }
#pragma unroll
            for (int j = 0; j < TN; j += 4) {
                float4 v = *(const float4*)&Bs[kk][tx*TN + j];
                b[j] = v.x; b[j+1] = v.y; b[j+2] = v.z; b[j+3] = v.w;
            }
#pragma unroll
            for (int i = 0; i < TM; i++)
#pragma unroll
                for (int j = 0; j < TN; j++)
                    acc[i][j] = fmaf(a[i], b[j], acc[i][j]);
        }
        __syncthreads();
    }

    const int N2 = N >> 1;
#pragma unroll
    for (int i = 0; i < TM; i++) {
        const int row = bm + ty*TM + i;
#pragma unroll
        for (int j = 0; j < TN; j += 4) {
            const int col = bn + tx*TN + j;
            float4 bv = *(const float4*)(bias + (size_t)row * bias_ld + col);
            float4 v;
            v.x = fmaxf(acc[i][j+0] + bv.x, 0.f);
            v.y = fmaxf(acc[i][j+1] + bv.y, 0.f);
            v.z = fmaxf(acc[i][j+2] + bv.z, 0.f);
            v.w = fmaxf(acc[i][j+3] + bv.w, 0.f);
            *(float4*)(C + (size_t)row * N + col) = v;
            uint32_t h, l;
            split_pack(v.x, v.y, h, l);
            Ch[(size_t)row * N2 + (col>>1)]     = h;
            Cl[(size_t)row * N2 + (col>>1)]     = l;
            split_pack(v.z, v.w, h, l);
            Ch[(size_t)row * N2 + (col>>1) + 1] = h;
            Cl[(size_t)row * N2 + (col>>1) + 1] = l;
        }
    }
}

// ---------------------------------------------------------------------------
// unified tensor GEMM, templated on BM (128 for biggemm, 64 for h1).
// 3-stage cp.async, 1 barrier/chunk, ldmatrix A frags, scalar B frags (R12).
// OUT=0: C fp32 = A@B + bias[N].  OUT=1: relu(A@B+bias) -> split Ch/Cl.
// ---------------------------------------------------------------------------
template<int OUT, int BM>
__global__ void __launch_bounds__(256, 2)
tcgemm_k(const uint32_t* __restrict__ AH, const uint32_t* __restrict__ AL,
         const uint32_t* __restrict__ BH, const uint32_t* __restrict__ BL,
         const float* __restrict__ bias, float* __restrict__ Cf,
         uint32_t* __restrict__ Ch, uint32_t* __restrict__ Cl,
         int M, int N, int K2)
{
    constexpr int MT       = BM / 32;            // m-tiles per warp (4 or 2)
    constexpr int AS_OFF_L = BM * 20 * 4;
    constexpr int BS_OFF_H = 2 * BM * 20 * 4;
    constexpr int BS_OFF_L = BS_OFF_H + 16*136*4;
    constexpr int STG_SZ   = BS_OFF_L + 16*136*4;

    extern __shared__ char dsm[];
    const uint32_t sb0 = smem_u32(dsm);

    const int tid  = threadIdx.x;
    const int bm   = blockIdx.y * BM;
    const int bn   = blockIdx.x * 128;
    const int warp = tid >> 5;
    const int lane = tid & 31;
    const int wm   = (warp >> 2) * (BM / 2);
    const int wn   = (warp & 3) * 32;
    const int gid  = lane >> 2;
    const int tig  = lane & 3;
    const int NC   = K2 / 16;

    const uint32_t lm_off =
        (uint32_t)(((wm + (lane & 15)) * 20 + ((lane >> 4) << 2)) * 4);

    float c[MT][4][4];
#pragma unroll
    for (int mt = 0; mt < MT; mt++)
#pragma unroll
        for (int nt = 0; nt < 4; nt++)
#pragma unroll
            for (int i = 0; i < 4; i++) c[mt][nt][i] = 0.f;

    auto issue = [&](int kc) {
        const uint32_t sb = sb0 + (kc % 3) * STG_SZ;
#pragma unroll
        for (int i = 0; i < BM/32; i++) {
            int f = tid + i * 256;
            int r = f >> 3, q = f & 7;
            uint32_t d = (uint32_t)(r * 20 + q * 2) * 4;
            size_t   s = (size_t)(bm + r) * K2 + kc * 16 + q * 2;
            CP8(sb + d,            (const char*)(AH + s));
            CP8(sb + AS_OFF_L + d, (const char*)(AL + s));
        }
#pragma unroll
        for (int i = 0; i < 2; i++) {
            int f = tid + i * 256;
            int r = f >> 5, q = f & 31;
            uint32_t d = (uint32_t)(r * 136 + q * 4) * 4;
            size_t   s = (size_t)(kc * 16 + r) * N + bn + q * 4;
            CP16(sb + BS_OFF_H + d, (const char*)(BH + s));
            CP16(sb + BS_OFF_L + d, (const char*)(BL + s));
        }
        CP_COMMIT();
    };

    issue(0);
    issue(1);

    for (int kc = 0; kc < NC; kc++) {
        if (kc + 1 < NC) asm volatile("cp.async.wait_group 1;" ::: "memory");
        else             asm volatile("cp.async.wait_group 0;" ::: "memory");
        __syncthreads();
        if (kc + 2 < NC) issue(kc + 2);

        const int st = kc % 3;
        const uint32_t sbase = sb0 + st * STG_SZ;
        const uint32_t* BsH = (const uint32_t*)(dsm + st * STG_SZ + BS_OFF_H);
        const uint32_t* BsL = (const uint32_t*)(dsm + st * STG_SZ + BS_OFF_L);

#pragma unroll
        for (int ks = 0; ks < 2; ks++) {
            const int pb = ks * 8;
            uint32_t afH[MT][4], afL[MT][4], bfH[4][2], bfL[4][2];
#pragma unroll
            for (int mt = 0; mt < MT; mt++) {
                uint32_t aH = sbase + lm_off + (uint32_t)((mt * 16 * 20 + pb) * 4);
                LDSM_X4(afH[mt][0], afH[mt][1], afH[mt][2], afH[mt][3], aH);
                LDSM_X4(afL[mt][0], afL[mt][1], afL[mt][2], afL[mt][3], aH + AS_OFF_L);
            }
#pragma unroll
            for (int nt = 0; nt < 4; nt++) {
                int cn = wn + nt * 8 + gid;
                bfH[nt][0] = BsH[(pb + tig    )*136 + cn];
                bfH[nt][1] = BsH[(pb + tig + 4)*136 + cn];
                bfL[nt][0] = BsL[(pb + tig    )*136 + cn];
                bfL[nt][1] = BsL[(pb + tig + 4)*136 + cn];
            }
#pragma unroll
            for (int mt = 0; mt < MT; mt++)
#pragma unroll
                for (int nt = 0; nt < 4; nt++) {
                    MMA_BF16(c[mt][nt][0], c[mt][nt][1], c[mt][nt][2], c[mt][nt][3],
                             afL[mt][0], afL[mt][1], afL[mt][2], afL[mt][3],
                             bfH[nt][0], bfH[nt][1]);
                    MMA_BF16(c[mt][nt][0], c[mt][nt][1], c[mt][nt][2], c[mt][nt][3],
                             afH[mt][0], afH[mt][1], afH[mt][2], afH[mt][3],
                             bfL[nt][0], bfL[nt][1]);
                    MMA_BF16(c[mt][nt][0], c[mt][nt][1], c[mt][nt][2], c[mt][nt][3],
                             afH[mt][0], afH[mt][1], afH[mt][2], afH[mt][3],
                             bfH[nt][0], bfH[nt][1]);
                }
        }
    }

    const int N2 = N >> 1;
#pragma unroll
    for (int mt = 0; mt < MT; mt++) {
        const int row = bm + wm + mt * 16 + gid;
#pragma unroll
        for (int nt = 0; nt < 4; nt++) {
            const int col = bn + wn + nt * 8 + tig * 2;
            float b0 = bias[col], b1 = bias[col + 1];
            if (OUT == 0) {
                float2 v0, v1;
                v0.x = c[mt][nt][0] + b0; v0.y = c[mt][nt][1] + b1;
                v1.x = c[mt][nt][2] + b0; v1.y = c[mt][nt][3] + b1;
                *(float2*)(Cf + (size_t)row * N + col)       = v0;
                *(float2*)(Cf + (size_t)(row + 8) * N + col) = v1;
            } else {
                float v00 = fmaxf(c[mt][nt][0] + b0, 0.f);
                float v01 = fmaxf(c[mt][nt][1] + b1, 0.f);
                float v10 = fmaxf(c[mt][nt][2] + b0, 0.f);
                float v11 = fmaxf(c[mt][nt][3] + b1, 0.f);
                uint32_t h, l;
                split_pack(v00, v01, h, l);
                Ch[(size_t)row * N2 + (col>>1)] = h;
                Cl[(size_t)row * N2 + (col>>1)] = l;
                split_pack(v10, v11, h, l);
                Ch[(size_t)(row+8) * N2 + (col>>1)] = h;
                Cl[(size_t)(row+8) * N2 + (col>>1)] = l;
            }
        }
    }
}

#define TC_SMEM_128 (3 * (2*128*20*4 + 2*16*136*4))   // 113664
#define TC_SMEM_64  (3 * (2*64*20*4  + 2*16*136*4))   // 82944

// ---------------------------------------------------------------------------
__global__ void __launch_bounds__(256)
einsum_k(const float* __restrict__ hU, const float* __restrict__ s,
         float* __restrict__ h2)
{
    __shared__ float hs[4][Kn];
    const int tid = threadIdx.x;
    const int r   = tid / Kn;
    const int j   = tid % Kn;
    const int b   = blockIdx.x * 4 + r;

    hs[r][j] = hU[(size_t)b * Kn + j];
    __syncthreads();

    const float* S = s + (size_t)b * SN + Dn;
    float acc = 0.f;
#pragma unroll
    for (int k = 0; k < Kn; k++)
        acc = fmaf(hs[r][k], S[(size_t)k * Kn + j], acc);
    h2[(size_t)b * Kn + j] = acc;
}

__global__ void __launch_bounds__(256)
outproj_k(const float* __restrict__ x, const float* __restrict__ W,
          const float* __restrict__ b, float* __restrict__ out)
{
    const int warp = (blockIdx.x * blockDim.x + threadIdx.x) >> 5;
    const int lane = threadIdx.x & 31;
    const float4* xr = (const float4*)(x + (size_t)warp * Dn);
    const float4* W4 = (const float4*)W;
    float acc = 0.f;
#pragma unroll
    for (int i = lane; i < Dn/4; i += 32) {
        float4 a = xr[i], w = W4[i];
        acc += a.x*w.x + a.y*w.y + a.z*w.z + a.w*w.w;
    }
#pragma unroll
    for (int o = 16; o; o >>= 1) acc += __shfl_xor_sync(0xFFFFFFFFu, acc, o);
    if (lane == 0) out[warp] = acc + b[0];
}

// ---------------------------------------------------------------------------
static void run_layer(const float* xin, bool first_layer,
                      const float* U, const float* V,
                      const float* hW1, const float* hb1,
                      const float* hW2, const float* hb2,
                      float* s, float* hU, float* h2,
                      uint32_t* h1h, uint32_t* h1l,
                      uint32_t* w2h, uint32_t* w2l,
                      uint32_t* w1h, uint32_t* w1l,
                      uint32_t* xh, uint32_t* xl,
                      float* xout)
{
    wsplit_k<<<(K2C*SN + 255)/256, 256>>>(hW2, w2h, w2l, K2C, SN);
    wsplit_k<<<(D2C*Hn + 255)/256, 256>>>(hW1, w1h, w1l, D2C, Hn);
    if (first_layer)
        xsplit_k<<<(Bn*D2C)/256, 256>>>(xin, xh, xl);

    // h1: BM=64 tiles -> grid (2, 128) = 256 CTAs (no launch starvation)
    tcgemm_k<1,64><<<dim3(Hn/128, Bn/64), 256, TC_SMEM_64>>>(
        xh, xl, w1h, w1l, hb1, nullptr, h1h, h1l, Bn, Hn, D2C);

    gemm_k<32,64,16,4,4><<<dim3(Kn/64, Bn/32), 128>>>(
        xin, U, hU, Bn, Kn, Dn);

    // biggemm: BM=128 (R12 config)
    tcgemm_k<0,128><<<dim3(SN/128, Bn/128), 256, TC_SMEM_128>>>(
        h1h, h1l, w2h, w2l, hb2, s, nullptr, nullptr, Bn, SN, K2C);

    einsum_k<<<Bn/4, 256>>>(hU, s, h2);

    vgemm_k<<<dim3(Dn/128, Bn/128), 256>>>(
        h2, V, s, SN, xout, xh, xl, Bn, Dn, Kn);
}

extern "C" void kernel_launch(void* const* d_in, const int* in_sizes, int n_in,
                              void* d_out, int out_size)
{
    cudaFuncSetAttribute((const void*)tcgemm_k<0,128>,
                         cudaFuncAttributeMaxDynamicSharedMemorySize, TC_SMEM_128);
    cudaFuncSetAttribute((const void*)tcgemm_k<1,64>,
                         cudaFuncAttributeMaxDynamicSharedMemorySize, TC_SMEM_64);

    const float* x    = (const float*)d_in[0];
    const float* Wout = (const float*)d_in[19];
    const float* bout = (const float*)d_in[20];

    float *s, *hU, *h2, *x1, *x2;
    uint32_t *h1h, *h1l, *w2h, *w2l, *w1h, *w1l, *xh, *xl;
    cudaGetSymbolAddress((void**)&s,   g_s);
    cudaGetSymbolAddress((void**)&hU,  g_hU);
    cudaGetSymbolAddress((void**)&h2,  g_h2);
    cudaGetSymbolAddress((void**)&x1,  g_x1);
    cudaGetSymbolAddress((void**)&x2,  g_x2);
    cudaGetSymbolAddress((void**)&h1h, g_h1h);
    cudaGetSymbolAddress((void**)&h1l, g_h1l);
    cudaGetSymbolAddress((void**)&w2h, g_w2h);
    cudaGetSymbolAddress((void**)&w2l, g_w2l);
    cudaGetSymbolAddress((void**)&w1h, g_w1h);
    cudaGetSymbolAddress((void**)&w1l, g_w1l);
    cudaGetSymbolAddress((void**)&xh,  g_xh);
    cudaGetSymbolAddress((void**)&xl,  g_xl);

    const float* U1  = (const float*)d_in[1];
    const float* V1  = (const float*)d_in[2];
    const float* W11 = (const float*)d_in[3];
    const float* b11 = (const float*)d_in[4];
    const float* W21 = (const float*)d_in[5];
    const float* b21 = (const float*)d_in[6];

    const float* U2  = (const float*)d_in[7];
    const float* V2  = (const float*)d_in[8];
    const float* W12 = (const float*)d_in[9];
    const float* b12 = (const float*)d_in[10];
    const float* W22 = (const float*)d_in[11];
    const float* b22 = (const float*)d_in[12];

    const float* U3  = (const float*)d_in[13];
    const float* V3  = (const float*)d_in[14];
    const float* W13 = (const float*)d_in[15];
    const float* b13 = (const float*)d_in[16];
    const float* W23 = (const float*)d_in[17];
    const float* b23 = (const float*)d_in[18];

    run_layer(x,  true,  U1, V1, W11, b11, W21, b21,
              s, hU, h2, h1h, h1l, w2h, w2l, w1h, w1l, xh, xl, x1);
    run_layer(x1, false, U2, V2, W12, b12, W22, b22,
              s, hU, h2, h1h, h1l, w2h, w2l, w1h, w1l, xh, xl, x2);
    run_layer(x2, false, U3, V3, W13, b13, W23, b23,
              s, hU, h2, h1h, h1l, w2h, w2l, w1h, w1l, xh, xl, x1);

    outproj_k<<<Bn/8, 256>>>(x1, Wout, bout, (float*)d_out);
}